// round 10
// baseline (speedup 1.0000x reference)
#include <cuda_runtime.h>

#define K1v 16
#define BATCH 16
#define CH 32
#define NP 4096
#define EDG (NP*K1v)          // 65536
#define TP 16                 // points per CTA
#define RR 256                // rows per CTA
#define INVC 0.9999950000374997f  // 1/sqrt(1+1e-5)

typedef unsigned long long u64;

// Scratch (no cudaMalloc allowed)
__device__ int   g_idx[BATCH*NP*K1v];     // 4 MB
__device__ float g_featT[BATCH*NP*CH];    // 8 MB (B,P,C)
__device__ u64   g_dup[4096];             // staging for dup'd weights

// Dup'd weights in constant memory, [k][o] layout (u64 = (w,w))
__constant__ __align__(16) u64 cW0h[1024];   // [32k][32o]
__constant__ __align__(16) u64 cW1 [1024];   // [32k][32o]
__constant__ __align__(16) u64 cW2 [2048];   // [32k][64o]

__device__ __forceinline__ u64 fma2(u64 a, u64 b, u64 c) {
    u64 d;
    asm("fma.rn.f32x2 %0, %1, %2, %3;" : "=l"(d) : "l"(a), "l"(b), "l"(c));
    return d;
}
__device__ __forceinline__ u64 pack2(float x, float y) {
    u64 d;
    asm("mov.b64 %0, {%1, %2};" : "=l"(d) : "f"(x), "f"(y));
    return d;
}
__device__ __forceinline__ void unpack2(u64 v, float& x, float& y) {
    asm("mov.b64 {%0, %1}, %2;" : "=f"(x), "=f"(y) : "l"(v));
}

// ---------------------------------------------------------------------------
// Duplicate weights into [k][o] u64 staging (then D2D-copied into constant)
// ---------------------------------------------------------------------------
__global__ void dup_kernel(const float* __restrict__ W0,
                           const float* __restrict__ W1,
                           const float* __restrict__ W2) {
    int t = blockIdx.x * 256 + threadIdx.x;   // 4096
    if (t < 1024) {
        int k = t >> 5, o = t & 31;
        float w = W0[o * 64 + 32 + k];        // high half
        g_dup[k * 32 + o] = pack2(w, w);
    } else if (t < 2048) {
        int i = t - 1024, k = i >> 5, o = i & 31;
        float w = W1[o * 32 + k];
        g_dup[1024 + k * 32 + o] = pack2(w, w);
    } else if (t < 4096) {
        int i = t - 2048, k = i >> 6, o = i & 63;
        float w = W2[o * 32 + k];
        g_dup[2048 + k * 64 + o] = pack2(w, w);
    }
}

// ---------------------------------------------------------------------------
// Edge preprocessing: prep (defaults + per-chunk break) -> scatter
// ---------------------------------------------------------------------------
__device__ int g_brk[BATCH*256];

__global__ void prep_kernel(const int* __restrict__ ef) {
    const int blk   = blockIdx.x;
    const int b     = blk >> 8;
    const int chunk = blk & 255;
    const int t     = threadIdx.x;         // 256
    const int e     = chunk * 256 + t;

    g_idx[(b << 16) | e] = NP - K1v + (e & 15);   // default idx0

    const int* __restrict__ pf = ef + (size_t)b * 2 * EDG;
    int brk = EDG;
    if (e > 0 && pf[e] == 0 && pf[e - 1] != 0) brk = e;

    __shared__ int s[256];
    s[t] = brk;
    __syncthreads();
    #pragma unroll
    for (int off = 128; off > 0; off >>= 1) {
        if (t < off) s[t] = min(s[t], s[t + off]);
        __syncthreads();
    }
    if (t == 0) g_brk[b * 256 + chunk] = s[0];
}

__global__ void scatter_kernel(const int* __restrict__ ef) {
    const int b  = blockIdx.y;
    const int e0 = blockIdx.x * 256;
    const int t  = threadIdx.x;
    const int e  = e0 + t;
    const int* __restrict__ pf = ef + (size_t)b * 2 * EDG;
    const int* __restrict__ tg = pf + EDG;

    __shared__ int s[272];
    __shared__ int sm2[256];
    sm2[t] = g_brk[b * 256 + t];
    for (int i = t; i < 272; i += 256) {
        int src = e0 - 16 + i;
        s[i] = (src >= 0) ? pf[src] : -1;
    }
    __syncthreads();
    #pragma unroll
    for (int off = 128; off > 0; off >>= 1) {
        if (t < off) sm2[t] = min(sm2[t], sm2[t + off]);
        __syncthreads();
    }
    const int broken = sm2[0];

    int v = s[t + 16];
    int j = 0, m = e, si = t + 16;
    while (m > 0 && j < 16 && s[si - 1] == v) { m--; si--; j++; }
    if (j < 16 && e < broken && (unsigned)v < (unsigned)NP)
        g_idx[(((size_t)b * NP + v) << 4) + j] = tg[e];
}

// ---------------------------------------------------------------------------
// Transpose features (B,C,P) -> (B,P,C)
// ---------------------------------------------------------------------------
__global__ void transpose_kernel(const float* __restrict__ f) {
    __shared__ float tile[32][33];
    int b  = blockIdx.y;
    int p0 = blockIdx.x * 32;
    int tx = threadIdx.x, ty = threadIdx.y;  // (32, 8)
    #pragma unroll
    for (int i = 0; i < 32; i += 8)
        tile[ty + i][tx] = f[((size_t)b * CH + ty + i) * NP + p0 + tx];
    __syncthreads();
    #pragma unroll
    for (int i = 0; i < 32; i += 8)
        g_featT[((size_t)b * NP + p0 + ty + i) * CH + tx] = tile[tx][ty + i];
}

// ---------------------------------------------------------------------------
// GEMM stage: o-sliced warps, weights from CONSTANT memory ([k][o] dup'd u64).
// Warp owns o-slice [o0, o0+8) over ALL 256 rows.
// Per k: 2x ulonglong2 LDS (x, 8 wf) + 4x LDC.128 (weights, const port).
// MODE 0: dst[o][r] = relu(acc*s + pb0[o][pt]);  MODE 1: bias b[o];
// MODE 2: red[o][pt] = sum over rows of relu(acc*s + b[o])  (shfl over lane&3).
// WSEL: 0=cW0h (OSTR 32), 1=cW1 (OSTR 32), 2=cW2 (OSTR 64).
// ---------------------------------------------------------------------------
template<int WSEL, int MODE>
__device__ __forceinline__ void gemm_stage(
    const float* __restrict__ src,   // [32][256]
    float*       __restrict__ dst,
    int o0,
    const float* __restrict__ scal, const float* __restrict__ bias,
    const float* __restrict__ pb0s,
    int lane)
{
    constexpr int OSTR = (WSEL == 2) ? 64 : 32;

    u64 acc[8][4];
    #pragma unroll
    for (int o = 0; o < 8; o++)
        #pragma unroll
        for (int j = 0; j < 4; j++) acc[o][j] = 0ull;

    const float* xb = src + lane * 4;

    #pragma unroll 8
    for (int k = 0; k < 32; k++) {
        u64 xp[4];
        {
            ulonglong2 x0 = *(const ulonglong2*)(xb + k * RR);
            ulonglong2 x1 = *(const ulonglong2*)(xb + k * RR + 128);
            xp[0] = x0.x; xp[1] = x0.y; xp[2] = x1.x; xp[3] = x1.y;
        }
        u64 wd[8];
        #pragma unroll
        for (int q = 0; q < 4; q++) {
            int idx = k * OSTR + o0 + q * 2;
            ulonglong2 wv;
            if constexpr (WSEL == 0)      wv = *(const ulonglong2*)&cW0h[idx];
            else if constexpr (WSEL == 1) wv = *(const ulonglong2*)&cW1[idx];
            else                          wv = *(const ulonglong2*)&cW2[idx];
            wd[q*2]   = wv.x;
            wd[q*2+1] = wv.y;
        }
        #pragma unroll
        for (int o = 0; o < 8; o++) {
            acc[o][0] = fma2(wd[o], xp[0], acc[o][0]);
            acc[o][1] = fma2(wd[o], xp[1], acc[o][1]);
            acc[o][2] = fma2(wd[o], xp[2], acc[o][2]);
            acc[o][3] = fma2(wd[o], xp[3], acc[o][3]);
        }
    }

    const int ptq = lane >> 2;   // + g*8

    #pragma unroll
    for (int o = 0; o < 8; o++) {
        int og = o0 + o;
        float s = scal[og];
        if (MODE == 2) {
            float bv = bias[og];
            #pragma unroll
            for (int g = 0; g < 2; g++) {
                float h0, h1, h2, h3;
                unpack2(acc[o][2*g],   h0, h1);
                unpack2(acc[o][2*g+1], h2, h3);
                float pa = fmaxf(fmaf(h0, s, bv), 0.f) + fmaxf(fmaf(h1, s, bv), 0.f)
                         + fmaxf(fmaf(h2, s, bv), 0.f) + fmaxf(fmaf(h3, s, bv), 0.f);
                pa += __shfl_xor_sync(0xffffffffu, pa, 1);
                pa += __shfl_xor_sync(0xffffffffu, pa, 2);
                if ((lane & 3) == 0)
                    dst[og * TP + g * 8 + ptq] = pa;
            }
        } else {
            #pragma unroll
            for (int g = 0; g < 2; g++) {
                float bv = (MODE == 0) ? pb0s[og * TP + g * 8 + ptq] : bias[og];
                float h0, h1, h2, h3;
                unpack2(acc[o][2*g],   h0, h1);
                unpack2(acc[o][2*g+1], h2, h3);
                h0 = fmaxf(fmaf(h0, s, bv), 0.f);
                h1 = fmaxf(fmaf(h1, s, bv), 0.f);
                h2 = fmaxf(fmaf(h2, s, bv), 0.f);
                h3 = fmaxf(fmaf(h3, s, bv), 0.f);
                *(float4*)(dst + og * RR + g * 128 + lane * 4)
                    = make_float4(h0, h1, h2, h3);
            }
        }
    }
}

// ---------------------------------------------------------------------------
// Main kernel, 128 threads, TP=16 points (256 rows), 3 CTAs/SM.
// Smem (float offsets), 18816 floats = 73.5 KB:
//   0    ss0  32 sb0  64 ss1  96 sb1  128 ss2  192 sb2  256 ssc  320 sbc
//   384  CF[32c][16]   896 pb0s[32o][16]   1408 red[64o][16]
//   2432 XA[32][256]   10624 XB[32][256]
// ---------------------------------------------------------------------------
#define SMEM_FLOATS 18816

__global__ void __launch_bounds__(128, 3) main_kernel(
    const float* __restrict__ W0, const float* __restrict__ g0, const float* __restrict__ bb0,
    const float* __restrict__ g1, const float* __restrict__ bb1,
    const float* __restrict__ g2, const float* __restrict__ bb2,
    const float* __restrict__ SW, const float* __restrict__ sg, const float* __restrict__ sb,
    float* __restrict__ out)
{
    extern __shared__ float sm[];
    float* ss0   = sm;
    float* sb0   = sm + 32;
    float* ss1   = sm + 64;
    float* sb1   = sm + 96;
    float* ss2   = sm + 128;
    float* sb2   = sm + 192;
    float* ssc   = sm + 256;
    float* sbc   = sm + 320;
    float* CF    = sm + 384;
    float* pb0s  = sm + 896;
    float* red   = sm + 1408;
    float* XA    = sm + 2432;
    float* XB    = sm + 10624;

    const int tid  = threadIdx.x;
    const int base = blockIdx.x * TP;
    const int b    = base >> 12;
    const int p0   = base & (NP - 1);

    if (tid < 32) { ss0[tid] = g0[tid] * INVC; sb0[tid] = bb0[tid];
                    ss1[tid] = g1[tid] * INVC; sb1[tid] = bb1[tid]; }
    else if (tid < 96) { int o = tid - 32;
                    ss2[o] = g2[o] * INVC; sb2[o] = bb2[o];
                    ssc[o] = sg[o] * INVC; sbc[o] = sb[o]; }

    const float* __restrict__ fT = g_featT + (size_t)b * NP * CH;

    // ---- stage CF[c][pt] ----
    {
        int pt = tid >> 3;
        int c0 = (tid & 7) * 4;
        float4 v = *(const float4*)(fT + (size_t)(p0 + pt) * CH + c0);
        CF[(c0+0) * TP + pt] = v.x;
        CF[(c0+1) * TP + pt] = v.y;
        CF[(c0+2) * TP + pt] = v.z;
        CF[(c0+3) * TP + pt] = v.w;
    }

    // ---- stage XH: thread handles rows 2*tid, 2*tid+1 (same pt) ----
    {
        int r0s = tid * 2;
        int pt  = r0s >> 4;
        int k0  = r0s & 15;
        const int* ipp = g_idx + (((size_t)b * NP + p0 + pt) << 4);
        int q0 = ipp[k0];
        int q1 = ipp[k0 + 1];
        const float4* qa = (const float4*)(fT + (size_t)q0 * CH);
        const float4* qb = (const float4*)(fT + (size_t)q1 * CH);
        const float4* pp = (const float4*)(fT + (size_t)(p0 + pt) * CH);
        #pragma unroll
        for (int i = 0; i < 8; i++) {
            float4 a0 = qa[i], a1 = qb[i], cv = pp[i];
            *(float2*)(XA + (4*i+0) * RR + r0s) = make_float2(a0.x - cv.x, a1.x - cv.x);
            *(float2*)(XA + (4*i+1) * RR + r0s) = make_float2(a0.y - cv.y, a1.y - cv.y);
            *(float2*)(XA + (4*i+2) * RR + r0s) = make_float2(a0.z - cv.z, a1.z - cv.z);
            *(float2*)(XA + (4*i+3) * RR + r0s) = make_float2(a0.w - cv.w, a1.w - cv.w);
        }
    }
    __syncthreads();

    // ---- pb0[o][pt]: W0 low half read from global (L2-resident, 4KB) ----
    {
        int pt  = tid & 15;
        int o0p = (tid >> 4) * 4;      // 8 groups x 4 o = 32 o
        float a[4] = {0.f, 0.f, 0.f, 0.f};
        #pragma unroll
        for (int j = 0; j < 4; j++) {
            const float* wr = W0 + (o0p + j) * 64;   // low half = first 32
            float acc = 0.f;
            #pragma unroll
            for (int c4 = 0; c4 < 8; c4++) {
                float4 w = *(const float4*)(wr + c4 * 4);
                acc = fmaf(w.x, CF[(c4*4+0) * TP + pt], acc);
                acc = fmaf(w.y, CF[(c4*4+1) * TP + pt], acc);
                acc = fmaf(w.z, CF[(c4*4+2) * TP + pt], acc);
                acc = fmaf(w.w, CF[(c4*4+3) * TP + pt], acc);
            }
            a[j] = acc;
        }
        #pragma unroll
        for (int j = 0; j < 4; j++) {
            int o = o0p + j;
            pb0s[o * TP + pt] = fmaf(a[j], ss0[o], sb0[o]);
        }
    }
    __syncthreads();

    const int w_   = tid >> 5;
    const int lane = tid & 31;

    gemm_stage<0, 0>(XA, XB, w_ * 8, ss0, sb0, pb0s, lane);
    __syncthreads();
    gemm_stage<1, 1>(XB, XA, w_ * 8, ss1, sb1, pb0s, lane);
    __syncthreads();
    gemm_stage<2, 2>(XA, red, w_ * 8,      ss2, sb2, pb0s, lane);
    gemm_stage<2, 2>(XA, red, 32 + w_ * 8, ss2, sb2, pb0s, lane);
    __syncthreads();

    // ---- shortcut + mean + final relu; SW read from global (L2, 8KB) ----
    {
        int pt  = tid & 15;
        int o0s = (tid >> 4) * 8;      // 8 groups x 8 o = 64 o
        float a[8];
        #pragma unroll
        for (int j = 0; j < 8; j++) a[j] = 0.f;
        #pragma unroll
        for (int j = 0; j < 8; j++) {
            const float* wr = SW + (o0s + j) * 32;
            float acc = 0.f;
            #pragma unroll
            for (int c4 = 0; c4 < 8; c4++) {
                float4 w = *(const float4*)(wr + c4 * 4);
                acc = fmaf(w.x, CF[(c4*4+0) * TP + pt], acc);
                acc = fmaf(w.y, CF[(c4*4+1) * TP + pt], acc);
                acc = fmaf(w.z, CF[(c4*4+2) * TP + pt], acc);
                acc = fmaf(w.w, CF[(c4*4+3) * TP + pt], acc);
            }
            a[j] = acc;
        }
        #pragma unroll
        for (int j = 0; j < 8; j++) {
            int o = o0s + j;
            float v = fmaf(a[j], ssc[o], sbc[o]) + red[o * TP + pt] * (1.0f / 16.0f);
            out[((size_t)b * 64 + o) * NP + p0 + pt] = fmaxf(v, 0.f);
        }
    }
}

// ---------------------------------------------------------------------------
extern "C" void kernel_launch(void* const* d_in, const int* in_sizes, int n_in,
                              void* d_out, int out_size)
{
    (void)in_sizes; (void)n_in; (void)out_size;
    const float* features = (const float*)d_in[1];
    const int*   ef       = (const int*)d_in[2];

    static bool init_done = false;
    static void* dup_addr = nullptr;
    if (!init_done) {
        cudaFuncSetAttribute(main_kernel,
                             cudaFuncAttributeMaxDynamicSharedMemorySize,
                             SMEM_FLOATS * (int)sizeof(float));
        cudaGetSymbolAddress(&dup_addr, g_dup);
        init_done = true;
    }

    dup_kernel<<<16, 256>>>((const float*)d_in[3], (const float*)d_in[6],
                            (const float*)d_in[9]);
    cudaMemcpyToSymbolAsync(cW0h, dup_addr, 1024 * sizeof(u64), 0,
                            cudaMemcpyDeviceToDevice, 0);
    cudaMemcpyToSymbolAsync(cW1, (const char*)dup_addr + 1024 * sizeof(u64),
                            1024 * sizeof(u64), 0, cudaMemcpyDeviceToDevice, 0);
    cudaMemcpyToSymbolAsync(cW2, (const char*)dup_addr + 2048 * sizeof(u64),
                            2048 * sizeof(u64), 0, cudaMemcpyDeviceToDevice, 0);

    prep_kernel<<<BATCH * 256, 256>>>(ef);
    {
        dim3 tg(EDG / 256, BATCH);
        scatter_kernel<<<tg, 256>>>(ef);
    }
    {
        dim3 tb(32, 8), tg(NP / 32, BATCH);
        transpose_kernel<<<tg, tb>>>(features);
    }
    main_kernel<<<(BATCH * NP) / TP, 128, SMEM_FLOATS * sizeof(float)>>>(
        (const float*)d_in[3],
        (const float*)d_in[4],  (const float*)d_in[5],
        (const float*)d_in[7],  (const float*)d_in[8],
        (const float*)d_in[10], (const float*)d_in[11],
        (const float*)d_in[12], (const float*)d_in[13], (const float*)d_in[14],
        (float*)d_out);
}

// round 11
// speedup vs baseline: 1.4896x; 1.4896x over previous
#include <cuda_runtime.h>

#define K1v 16
#define BATCH 16
#define CH 32
#define NP 4096
#define EDG (NP*K1v)          // 65536
#define TP 16                 // points per CTA
#define RR 256                // rows per CTA
#define INVC 0.9999950000374997f  // 1/sqrt(1+1e-5)

typedef unsigned long long u64;

// Scratch (no cudaMalloc allowed)
__device__ int   g_idx[BATCH*NP*K1v];     // 4 MB
__device__ float g_featT[BATCH*NP*CH];    // 8 MB (B,P,C)
__device__ int   g_brk[BATCH*256];        // per-chunk first-break

__device__ __forceinline__ u64 fma2(u64 a, u64 b, u64 c) {
    u64 d;
    asm("fma.rn.f32x2 %0, %1, %2, %3;" : "=l"(d) : "l"(a), "l"(b), "l"(c));
    return d;
}
__device__ __forceinline__ u64 pack2(float x, float y) {
    u64 d;
    asm("mov.b64 %0, {%1, %2};" : "=l"(d) : "f"(x), "f"(y));
    return d;
}
__device__ __forceinline__ void unpack2(u64 v, float& x, float& y) {
    asm("mov.b64 {%0, %1}, %2;" : "=f"(x), "=f"(y) : "l"(v));
}

// ---------------------------------------------------------------------------
// Edge preprocessing: prep (defaults + per-chunk break) -> scatter
// ---------------------------------------------------------------------------
__global__ void prep_kernel(const int* __restrict__ ef) {
    const int blk   = blockIdx.x;
    const int b     = blk >> 8;
    const int chunk = blk & 255;
    const int t     = threadIdx.x;         // 256
    const int e     = chunk * 256 + t;

    g_idx[(b << 16) | e] = NP - K1v + (e & 15);   // default idx0

    const int* __restrict__ pf = ef + (size_t)b * 2 * EDG;
    int brk = EDG;
    if (e > 0 && pf[e] == 0 && pf[e - 1] != 0) brk = e;

    __shared__ int s[256];
    s[t] = brk;
    __syncthreads();
    #pragma unroll
    for (int off = 128; off > 0; off >>= 1) {
        if (t < off) s[t] = min(s[t], s[t + off]);
        __syncthreads();
    }
    if (t == 0) g_brk[b * 256 + chunk] = s[0];
}

__global__ void scatter_kernel(const int* __restrict__ ef) {
    const int b  = blockIdx.y;
    const int e0 = blockIdx.x * 256;
    const int t  = threadIdx.x;
    const int e  = e0 + t;
    const int* __restrict__ pf = ef + (size_t)b * 2 * EDG;
    const int* __restrict__ tg = pf + EDG;

    __shared__ int s[272];
    __shared__ int sm2[256];
    sm2[t] = g_brk[b * 256 + t];
    for (int i = t; i < 272; i += 256) {
        int src = e0 - 16 + i;
        s[i] = (src >= 0) ? pf[src] : -1;
    }
    __syncthreads();
    #pragma unroll
    for (int off = 128; off > 0; off >>= 1) {
        if (t < off) sm2[t] = min(sm2[t], sm2[t + off]);
        __syncthreads();
    }
    const int broken = sm2[0];

    int v = s[t + 16];
    int j = 0, m = e, si = t + 16;
    while (m > 0 && j < 16 && s[si - 1] == v) { m--; si--; j++; }
    if (j < 16 && e < broken && (unsigned)v < (unsigned)NP)
        g_idx[(((size_t)b * NP + v) << 4) + j] = tg[e];
}

// ---------------------------------------------------------------------------
// Transpose features (B,C,P) -> (B,P,C)
// ---------------------------------------------------------------------------
__global__ void transpose_kernel(const float* __restrict__ f) {
    __shared__ float tile[32][33];
    int b  = blockIdx.y;
    int p0 = blockIdx.x * 32;
    int tx = threadIdx.x, ty = threadIdx.y;  // (32, 8)
    #pragma unroll
    for (int i = 0; i < 32; i += 8)
        tile[ty + i][tx] = f[((size_t)b * CH + ty + i) * NP + p0 + tx];
    __syncthreads();
    #pragma unroll
    for (int i = 0; i < 32; i += 8)
        g_featT[((size_t)b * NP + p0 + ty + i) * CH + tx] = tile[tx][ty + i];
}

// ---------------------------------------------------------------------------
// GEMM stage: o-sliced warps; weights = scalar uniform LDG from GLOBAL
// (all lanes same address -> 1 sector broadcast; W arrays are L1-resident).
// Warp owns o-slice [o0, o0+8) over ALL 256 rows.
// X: 2x ulonglong2 LDS per k (8 wf, conflict-free contiguous phases).
// MODE 0: dst[o][r] = relu(acc*s + pb0[o][pt]);  MODE 1: bias b[o];
// MODE 2: red[o][pt] = sum over rows of relu(acc*s + b[o])  (shfl over lane&3).
// ---------------------------------------------------------------------------
template<int MODE>
__device__ __forceinline__ void gemm_stage(
    const float* __restrict__ src,   // [32][256] smem
    float*       __restrict__ dst,   // smem
    const float* __restrict__ Wg,    // global, [o][k] rows of length OSTR
    int OSTR, int o0,
    const float* __restrict__ scal, const float* __restrict__ bias,
    const float* __restrict__ pb0s,
    int lane)
{
    u64 acc[8][4];
    #pragma unroll
    for (int o = 0; o < 8; o++)
        #pragma unroll
        for (int j = 0; j < 4; j++) acc[o][j] = 0ull;

    const float* xb = src + lane * 4;
    const float* wb = Wg + o0 * OSTR;

    #pragma unroll 4
    for (int k = 0; k < 32; k++) {
        u64 xp[4];
        {
            ulonglong2 x0 = *(const ulonglong2*)(xb + k * RR);
            ulonglong2 x1 = *(const ulonglong2*)(xb + k * RR + 128);
            xp[0] = x0.x; xp[1] = x0.y; xp[2] = x1.x; xp[3] = x1.y;
        }
        #pragma unroll
        for (int o = 0; o < 8; o++) {
            float wv = __ldg(wb + o * OSTR + k);   // scalar uniform LDG broadcast
            u64 wd = pack2(wv, wv);
            acc[o][0] = fma2(wd, xp[0], acc[o][0]);
            acc[o][1] = fma2(wd, xp[1], acc[o][1]);
            acc[o][2] = fma2(wd, xp[2], acc[o][2]);
            acc[o][3] = fma2(wd, xp[3], acc[o][3]);
        }
    }

    const int ptq = lane >> 2;   // + g*8

    #pragma unroll
    for (int o = 0; o < 8; o++) {
        int og = o0 + o;
        float s = scal[og];
        if (MODE == 2) {
            float bv = bias[og];
            #pragma unroll
            for (int g = 0; g < 2; g++) {
                float h0, h1, h2, h3;
                unpack2(acc[o][2*g],   h0, h1);
                unpack2(acc[o][2*g+1], h2, h3);
                float pa = fmaxf(fmaf(h0, s, bv), 0.f) + fmaxf(fmaf(h1, s, bv), 0.f)
                         + fmaxf(fmaf(h2, s, bv), 0.f) + fmaxf(fmaf(h3, s, bv), 0.f);
                pa += __shfl_xor_sync(0xffffffffu, pa, 1);
                pa += __shfl_xor_sync(0xffffffffu, pa, 2);
                if ((lane & 3) == 0)
                    dst[og * TP + g * 8 + ptq] = pa;
            }
        } else {
            #pragma unroll
            for (int g = 0; g < 2; g++) {
                float bv = (MODE == 0) ? pb0s[og * TP + g * 8 + ptq] : bias[og];
                float h0, h1, h2, h3;
                unpack2(acc[o][2*g],   h0, h1);
                unpack2(acc[o][2*g+1], h2, h3);
                h0 = fmaxf(fmaf(h0, s, bv), 0.f);
                h1 = fmaxf(fmaf(h1, s, bv), 0.f);
                h2 = fmaxf(fmaf(h2, s, bv), 0.f);
                h3 = fmaxf(fmaf(h3, s, bv), 0.f);
                *(float4*)(dst + og * RR + g * 128 + lane * 4)
                    = make_float4(h0, h1, h2, h3);
            }
        }
    }
}

// ---------------------------------------------------------------------------
// Main kernel, 128 threads, TP=16 points (256 rows), 3 CTAs/SM.
// Smem (float offsets), 18816 floats = 73.5 KB:
//   0    ss0  32 sb0  64 ss1  96 sb1  128 ss2  192 sb2  256 ssc  320 sbc
//   384  CF[32c][16]   896 pb0s[32o][16]   1408 red[64o][16]
//   2432 XA[32][256]   10624 XB[32][256]
// ---------------------------------------------------------------------------
#define SMEM_FLOATS 18816

__global__ void __launch_bounds__(128, 3) main_kernel(
    const float* __restrict__ W0, const float* __restrict__ g0, const float* __restrict__ bb0,
    const float* __restrict__ W1, const float* __restrict__ g1, const float* __restrict__ bb1,
    const float* __restrict__ W2, const float* __restrict__ g2, const float* __restrict__ bb2,
    const float* __restrict__ SW, const float* __restrict__ sg, const float* __restrict__ sb,
    float* __restrict__ out)
{
    extern __shared__ float sm[];
    float* ss0   = sm;
    float* sb0   = sm + 32;
    float* ss1   = sm + 64;
    float* sb1   = sm + 96;
    float* ss2   = sm + 128;
    float* sb2   = sm + 192;
    float* ssc   = sm + 256;
    float* sbc   = sm + 320;
    float* CF    = sm + 384;
    float* pb0s  = sm + 896;
    float* red   = sm + 1408;
    float* XA    = sm + 2432;
    float* XB    = sm + 10624;

    const int tid  = threadIdx.x;
    const int base = blockIdx.x * TP;
    const int b    = base >> 12;
    const int p0   = base & (NP - 1);

    if (tid < 32) { ss0[tid] = g0[tid] * INVC; sb0[tid] = bb0[tid];
                    ss1[tid] = g1[tid] * INVC; sb1[tid] = bb1[tid]; }
    else if (tid < 96) { int o = tid - 32;
                    ss2[o] = g2[o] * INVC; sb2[o] = bb2[o];
                    ssc[o] = sg[o] * INVC; sbc[o] = sb[o]; }

    const float* __restrict__ fT = g_featT + (size_t)b * NP * CH;

    // ---- stage CF[c][pt] ----
    {
        int pt = tid >> 3;
        int c0 = (tid & 7) * 4;
        float4 v = *(const float4*)(fT + (size_t)(p0 + pt) * CH + c0);
        CF[(c0+0) * TP + pt] = v.x;
        CF[(c0+1) * TP + pt] = v.y;
        CF[(c0+2) * TP + pt] = v.z;
        CF[(c0+3) * TP + pt] = v.w;
    }

    // ---- stage XH: thread handles rows 2*tid, 2*tid+1 (same pt) ----
    {
        int r0s = tid * 2;
        int pt  = r0s >> 4;
        int k0  = r0s & 15;
        const int* ipp = g_idx + (((size_t)b * NP + p0 + pt) << 4);
        int q0 = ipp[k0];
        int q1 = ipp[k0 + 1];
        const float4* qa = (const float4*)(fT + (size_t)q0 * CH);
        const float4* qb = (const float4*)(fT + (size_t)q1 * CH);
        const float4* pp = (const float4*)(fT + (size_t)(p0 + pt) * CH);
        #pragma unroll
        for (int i = 0; i < 8; i++) {
            float4 a0 = qa[i], a1 = qb[i], cv = pp[i];
            *(float2*)(XA + (4*i+0) * RR + r0s) = make_float2(a0.x - cv.x, a1.x - cv.x);
            *(float2*)(XA + (4*i+1) * RR + r0s) = make_float2(a0.y - cv.y, a1.y - cv.y);
            *(float2*)(XA + (4*i+2) * RR + r0s) = make_float2(a0.z - cv.z, a1.z - cv.z);
            *(float2*)(XA + (4*i+3) * RR + r0s) = make_float2(a0.w - cv.w, a1.w - cv.w);
        }
    }
    __syncthreads();

    // ---- pb0[o][pt]: W0 low half read from global (L2/L1-resident, 4KB) ----
    {
        int pt  = tid & 15;
        int o0p = (tid >> 4) * 4;      // 8 groups x 4 o = 32 o
        float a[4] = {0.f, 0.f, 0.f, 0.f};
        #pragma unroll
        for (int j = 0; j < 4; j++) {
            const float* wr = W0 + (o0p + j) * 64;   // low half = first 32
            float acc = 0.f;
            #pragma unroll
            for (int c4 = 0; c4 < 8; c4++) {
                float4 w = *(const float4*)(wr + c4 * 4);
                acc = fmaf(w.x, CF[(c4*4+0) * TP + pt], acc);
                acc = fmaf(w.y, CF[(c4*4+1) * TP + pt], acc);
                acc = fmaf(w.z, CF[(c4*4+2) * TP + pt], acc);
                acc = fmaf(w.w, CF[(c4*4+3) * TP + pt], acc);
            }
            a[j] = acc;
        }
        #pragma unroll
        for (int j = 0; j < 4; j++) {
            int o = o0p + j;
            pb0s[o * TP + pt] = fmaf(a[j], ss0[o], sb0[o]);
        }
    }
    __syncthreads();

    const int w_   = tid >> 5;
    const int lane = tid & 31;

    gemm_stage<0>(XA, XB, W0 + 32, 64, w_ * 8, ss0, sb0, pb0s, lane);
    __syncthreads();
    gemm_stage<1>(XB, XA, W1, 32, w_ * 8, ss1, sb1, pb0s, lane);
    __syncthreads();
    gemm_stage<2>(XA, red, W2, 32, w_ * 8,      ss2, sb2, pb0s, lane);
    gemm_stage<2>(XA, red, W2, 32, 32 + w_ * 8, ss2, sb2, pb0s, lane);
    __syncthreads();

    // ---- shortcut + mean + final relu; SW read from global (8KB) ----
    {
        int pt  = tid & 15;
        int o0s = (tid >> 4) * 8;      // 8 groups x 8 o = 64 o
        float a[8];
        #pragma unroll
        for (int j = 0; j < 8; j++) a[j] = 0.f;
        #pragma unroll
        for (int j = 0; j < 8; j++) {
            const float* wr = SW + (o0s + j) * 32;
            float acc = 0.f;
            #pragma unroll
            for (int c4 = 0; c4 < 8; c4++) {
                float4 w = *(const float4*)(wr + c4 * 4);
                acc = fmaf(w.x, CF[(c4*4+0) * TP + pt], acc);
                acc = fmaf(w.y, CF[(c4*4+1) * TP + pt], acc);
                acc = fmaf(w.z, CF[(c4*4+2) * TP + pt], acc);
                acc = fmaf(w.w, CF[(c4*4+3) * TP + pt], acc);
            }
            a[j] = acc;
        }
        #pragma unroll
        for (int j = 0; j < 8; j++) {
            int o = o0s + j;
            float v = fmaf(a[j], ssc[o], sbc[o]) + red[o * TP + pt] * (1.0f / 16.0f);
            out[((size_t)b * 64 + o) * NP + p0 + pt] = fmaxf(v, 0.f);
        }
    }
}

// ---------------------------------------------------------------------------
extern "C" void kernel_launch(void* const* d_in, const int* in_sizes, int n_in,
                              void* d_out, int out_size)
{
    (void)in_sizes; (void)n_in; (void)out_size;
    const float* features = (const float*)d_in[1];
    const int*   ef       = (const int*)d_in[2];

    static bool attr_set = false;
    if (!attr_set) {
        cudaFuncSetAttribute(main_kernel,
                             cudaFuncAttributeMaxDynamicSharedMemorySize,
                             SMEM_FLOATS * (int)sizeof(float));
        attr_set = true;
    }

    prep_kernel<<<BATCH * 256, 256>>>(ef);
    {
        dim3 tg(EDG / 256, BATCH);
        scatter_kernel<<<tg, 256>>>(ef);
    }
    {
        dim3 tb(32, 8), tg(NP / 32, BATCH);
        transpose_kernel<<<tg, tb>>>(features);
    }
    main_kernel<<<(BATCH * NP) / TP, 128, SMEM_FLOATS * sizeof(float)>>>(
        (const float*)d_in[3],  (const float*)d_in[4],  (const float*)d_in[5],
        (const float*)d_in[6],  (const float*)d_in[7],  (const float*)d_in[8],
        (const float*)d_in[9],  (const float*)d_in[10], (const float*)d_in[11],
        (const float*)d_in[12], (const float*)d_in[13], (const float*)d_in[14],
        (float*)d_out);
}

// round 12
// speedup vs baseline: 1.6152x; 1.0843x over previous
#include <cuda_runtime.h>

#define K1v 16
#define BATCH 16
#define CH 32
#define NP 4096
#define EDG (NP*K1v)          // 65536
#define TP 16                 // points per CTA
#define RR 256                // rows per CTA
#define INVC 0.9999950000374997f  // 1/sqrt(1+1e-5)

typedef unsigned long long u64;

// Scratch (no cudaMalloc allowed)
__device__ int   g_idx[BATCH*NP*K1v];     // 4 MB
__device__ float g_featT[BATCH*NP*CH];    // 8 MB (B,P,C)
__device__ int   g_brk[BATCH*256];        // per-chunk first-break
__device__ float g_wT[4096];              // weights transposed to [k][o]

__device__ __forceinline__ u64 fma2(u64 a, u64 b, u64 c) {
    u64 d;
    asm("fma.rn.f32x2 %0, %1, %2, %3;" : "=l"(d) : "l"(a), "l"(b), "l"(c));
    return d;
}
__device__ __forceinline__ u64 pack2(float x, float y) {
    u64 d;
    asm("mov.b64 %0, {%1, %2};" : "=l"(d) : "f"(x), "f"(y));
    return d;
}
__device__ __forceinline__ void unpack2(u64 v, float& x, float& y) {
    asm("mov.b64 {%0, %1}, %2;" : "=f"(x), "=f"(y) : "l"(v));
}

// ---------------------------------------------------------------------------
// Weight transpose to [k][o]:  g_wT[0:1024)=W0h, [1024:2048)=W1, [2048:4096)=W2
// ---------------------------------------------------------------------------
__global__ void wprep_kernel(const float* __restrict__ W0,
                             const float* __restrict__ W1,
                             const float* __restrict__ W2) {
    int t = blockIdx.x * 256 + threadIdx.x;   // 4096
    if (t < 1024) {
        int k = t >> 5, o = t & 31;
        g_wT[k * 32 + o] = W0[o * 64 + 32 + k];       // high half of W0
    } else if (t < 2048) {
        int i = t - 1024, k = i >> 5, o = i & 31;
        g_wT[1024 + k * 32 + o] = W1[o * 32 + k];
    } else {
        int i = t - 2048, k = i >> 6, o = i & 63;
        g_wT[2048 + k * 64 + o] = W2[o * 32 + k];
    }
}

// ---------------------------------------------------------------------------
// Edge preprocessing: prep (defaults + per-chunk break) -> scatter
// ---------------------------------------------------------------------------
__global__ void prep_kernel(const int* __restrict__ ef) {
    const int blk   = blockIdx.x;
    const int b     = blk >> 8;
    const int chunk = blk & 255;
    const int t     = threadIdx.x;         // 256
    const int e     = chunk * 256 + t;

    g_idx[(b << 16) | e] = NP - K1v + (e & 15);   // default idx0

    const int* __restrict__ pf = ef + (size_t)b * 2 * EDG;
    int brk = EDG;
    if (e > 0 && pf[e] == 0 && pf[e - 1] != 0) brk = e;

    __shared__ int s[256];
    s[t] = brk;
    __syncthreads();
    #pragma unroll
    for (int off = 128; off > 0; off >>= 1) {
        if (t < off) s[t] = min(s[t], s[t + off]);
        __syncthreads();
    }
    if (t == 0) g_brk[b * 256 + chunk] = s[0];
}

__global__ void scatter_kernel(const int* __restrict__ ef) {
    const int b  = blockIdx.y;
    const int e0 = blockIdx.x * 256;
    const int t  = threadIdx.x;
    const int e  = e0 + t;
    const int* __restrict__ pf = ef + (size_t)b * 2 * EDG;
    const int* __restrict__ tg = pf + EDG;

    __shared__ int s[272];
    __shared__ int sm2[256];
    sm2[t] = g_brk[b * 256 + t];
    for (int i = t; i < 272; i += 256) {
        int src = e0 - 16 + i;
        s[i] = (src >= 0) ? pf[src] : -1;
    }
    __syncthreads();
    #pragma unroll
    for (int off = 128; off > 0; off >>= 1) {
        if (t < off) sm2[t] = min(sm2[t], sm2[t + off]);
        __syncthreads();
    }
    const int broken = sm2[0];

    int v = s[t + 16];
    int j = 0, m = e, si = t + 16;
    while (m > 0 && j < 16 && s[si - 1] == v) { m--; si--; j++; }
    if (j < 16 && e < broken && (unsigned)v < (unsigned)NP)
        g_idx[(((size_t)b * NP + v) << 4) + j] = tg[e];
}

// ---------------------------------------------------------------------------
// Transpose features (B,C,P) -> (B,P,C)
// ---------------------------------------------------------------------------
__global__ void transpose_kernel(const float* __restrict__ f) {
    __shared__ float tile[32][33];
    int b  = blockIdx.y;
    int p0 = blockIdx.x * 32;
    int tx = threadIdx.x, ty = threadIdx.y;  // (32, 8)
    #pragma unroll
    for (int i = 0; i < 32; i += 8)
        tile[ty + i][tx] = f[((size_t)b * CH + ty + i) * NP + p0 + tx];
    __syncthreads();
    #pragma unroll
    for (int i = 0; i < 32; i += 8)
        g_featT[((size_t)b * NP + p0 + ty + i) * CH + tx] = tile[tx][ty + i];
}

// ---------------------------------------------------------------------------
// GEMM stage: o-sliced warps; weights from global [k][o] via 2x uniform
// LDG.128 per k (2 wavefronts) + 8 pack MOVs (alu pipe).
// Warp owns o-slice [o0, o0+8) over ALL 256 rows.
// X: 2x ulonglong2 LDS per k (8 wf, conflict-free contiguous phases).
// MODE 0: dst[o][r] = relu(acc*s + pb0[o][pt]);  MODE 1: bias b[o];
// MODE 2: red[o][pt] = sum over rows of relu(acc*s + b[o])  (shfl over lane&3).
// ---------------------------------------------------------------------------
template<int MODE>
__device__ __forceinline__ void gemm_stage(
    const float* __restrict__ src,   // [32][256] smem
    float*       __restrict__ dst,   // smem
    const float* __restrict__ WkT,   // global, [k][Ototal]
    int OSTR, int o0,
    const float* __restrict__ scal, const float* __restrict__ bias,
    const float* __restrict__ pb0s,
    int lane)
{
    u64 acc[8][4];
    #pragma unroll
    for (int o = 0; o < 8; o++)
        #pragma unroll
        for (int j = 0; j < 4; j++) acc[o][j] = 0ull;

    const float* xb = src + lane * 4;
    const float* wb = WkT + o0;

    #pragma unroll 4
    for (int k = 0; k < 32; k++) {
        u64 xp[4];
        {
            ulonglong2 x0 = *(const ulonglong2*)(xb + k * RR);
            ulonglong2 x1 = *(const ulonglong2*)(xb + k * RR + 128);
            xp[0] = x0.x; xp[1] = x0.y; xp[2] = x1.x; xp[3] = x1.y;
        }
        const float4* w4 = (const float4*)(wb + k * OSTR);
        float4 wa = __ldg(w4);
        float4 wc = __ldg(w4 + 1);
        u64 wd[8] = { pack2(wa.x,wa.x), pack2(wa.y,wa.y),
                      pack2(wa.z,wa.z), pack2(wa.w,wa.w),
                      pack2(wc.x,wc.x), pack2(wc.y,wc.y),
                      pack2(wc.z,wc.z), pack2(wc.w,wc.w) };
        #pragma unroll
        for (int o = 0; o < 8; o++) {
            acc[o][0] = fma2(wd[o], xp[0], acc[o][0]);
            acc[o][1] = fma2(wd[o], xp[1], acc[o][1]);
            acc[o][2] = fma2(wd[o], xp[2], acc[o][2]);
            acc[o][3] = fma2(wd[o], xp[3], acc[o][3]);
        }
    }

    const int ptq = lane >> 2;   // + g*8

    #pragma unroll
    for (int o = 0; o < 8; o++) {
        int og = o0 + o;
        float s = scal[og];
        if (MODE == 2) {
            float bv = bias[og];
            #pragma unroll
            for (int g = 0; g < 2; g++) {
                float h0, h1, h2, h3;
                unpack2(acc[o][2*g],   h0, h1);
                unpack2(acc[o][2*g+1], h2, h3);
                float pa = fmaxf(fmaf(h0, s, bv), 0.f) + fmaxf(fmaf(h1, s, bv), 0.f)
                         + fmaxf(fmaf(h2, s, bv), 0.f) + fmaxf(fmaf(h3, s, bv), 0.f);
                pa += __shfl_xor_sync(0xffffffffu, pa, 1);
                pa += __shfl_xor_sync(0xffffffffu, pa, 2);
                if ((lane & 3) == 0)
                    dst[og * TP + g * 8 + ptq] = pa;
            }
        } else {
            #pragma unroll
            for (int g = 0; g < 2; g++) {
                float bv = (MODE == 0) ? pb0s[og * TP + g * 8 + ptq] : bias[og];
                float h0, h1, h2, h3;
                unpack2(acc[o][2*g],   h0, h1);
                unpack2(acc[o][2*g+1], h2, h3);
                h0 = fmaxf(fmaf(h0, s, bv), 0.f);
                h1 = fmaxf(fmaf(h1, s, bv), 0.f);
                h2 = fmaxf(fmaf(h2, s, bv), 0.f);
                h3 = fmaxf(fmaf(h3, s, bv), 0.f);
                *(float4*)(dst + og * RR + g * 128 + lane * 4)
                    = make_float4(h0, h1, h2, h3);
            }
        }
    }
}

// ---------------------------------------------------------------------------
// Main kernel, 128 threads, TP=16 points (256 rows), 3 CTAs/SM.
// Smem (float offsets), 18816 floats = 73.5 KB:
//   0    ss0  32 sb0  64 ss1  96 sb1  128 ss2  192 sb2  256 ssc  320 sbc
//   384  CF[32c][16]   896 pb0s[32o][16]   1408 red[64o][16]
//   2432 XA[32][256]   10624 XB[32][256]
// ---------------------------------------------------------------------------
#define SMEM_FLOATS 18816

__global__ void __launch_bounds__(128, 3) main_kernel(
    const float* __restrict__ W0, const float* __restrict__ g0, const float* __restrict__ bb0,
    const float* __restrict__ g1, const float* __restrict__ bb1,
    const float* __restrict__ g2, const float* __restrict__ bb2,
    const float* __restrict__ SW, const float* __restrict__ sg, const float* __restrict__ sb,
    float* __restrict__ out)
{
    extern __shared__ float sm[];
    float* ss0   = sm;
    float* sb0   = sm + 32;
    float* ss1   = sm + 64;
    float* sb1   = sm + 96;
    float* ss2   = sm + 128;
    float* sb2   = sm + 192;
    float* ssc   = sm + 256;
    float* sbc   = sm + 320;
    float* CF    = sm + 384;
    float* pb0s  = sm + 896;
    float* red   = sm + 1408;
    float* XA    = sm + 2432;
    float* XB    = sm + 10624;

    const int tid  = threadIdx.x;
    const int base = blockIdx.x * TP;
    const int b    = base >> 12;
    const int p0   = base & (NP - 1);

    if (tid < 32) { ss0[tid] = g0[tid] * INVC; sb0[tid] = bb0[tid];
                    ss1[tid] = g1[tid] * INVC; sb1[tid] = bb1[tid]; }
    else if (tid < 96) { int o = tid - 32;
                    ss2[o] = g2[o] * INVC; sb2[o] = bb2[o];
                    ssc[o] = sg[o] * INVC; sbc[o] = sb[o]; }

    const float* __restrict__ fT = g_featT + (size_t)b * NP * CH;

    // ---- stage CF[c][pt] ----
    {
        int pt = tid >> 3;
        int c0 = (tid & 7) * 4;
        float4 v = *(const float4*)(fT + (size_t)(p0 + pt) * CH + c0);
        CF[(c0+0) * TP + pt] = v.x;
        CF[(c0+1) * TP + pt] = v.y;
        CF[(c0+2) * TP + pt] = v.z;
        CF[(c0+3) * TP + pt] = v.w;
    }

    // ---- stage XH: thread handles rows 2*tid, 2*tid+1 (same pt) ----
    {
        int r0s = tid * 2;
        int pt  = r0s >> 4;
        int k0  = r0s & 15;
        const int* ipp = g_idx + (((size_t)b * NP + p0 + pt) << 4);
        int q0 = ipp[k0];
        int q1 = ipp[k0 + 1];
        const float4* qa = (const float4*)(fT + (size_t)q0 * CH);
        const float4* qb = (const float4*)(fT + (size_t)q1 * CH);
        const float4* pp = (const float4*)(fT + (size_t)(p0 + pt) * CH);
        #pragma unroll
        for (int i = 0; i < 8; i++) {
            float4 a0 = qa[i], a1 = qb[i], cv = pp[i];
            *(float2*)(XA + (4*i+0) * RR + r0s) = make_float2(a0.x - cv.x, a1.x - cv.x);
            *(float2*)(XA + (4*i+1) * RR + r0s) = make_float2(a0.y - cv.y, a1.y - cv.y);
            *(float2*)(XA + (4*i+2) * RR + r0s) = make_float2(a0.z - cv.z, a1.z - cv.z);
            *(float2*)(XA + (4*i+3) * RR + r0s) = make_float2(a0.w - cv.w, a1.w - cv.w);
        }
    }
    __syncthreads();

    // ---- pb0[o][pt]: W0 low half read from global (L2/L1-resident, 4KB) ----
    {
        int pt  = tid & 15;
        int o0p = (tid >> 4) * 4;      // 8 groups x 4 o = 32 o
        float a[4] = {0.f, 0.f, 0.f, 0.f};
        #pragma unroll
        for (int j = 0; j < 4; j++) {
            const float* wr = W0 + (o0p + j) * 64;   // low half = first 32
            float acc = 0.f;
            #pragma unroll
            for (int c4 = 0; c4 < 8; c4++) {
                float4 w = *(const float4*)(wr + c4 * 4);
                acc = fmaf(w.x, CF[(c4*4+0) * TP + pt], acc);
                acc = fmaf(w.y, CF[(c4*4+1) * TP + pt], acc);
                acc = fmaf(w.z, CF[(c4*4+2) * TP + pt], acc);
                acc = fmaf(w.w, CF[(c4*4+3) * TP + pt], acc);
            }
            a[j] = acc;
        }
        #pragma unroll
        for (int j = 0; j < 4; j++) {
            int o = o0p + j;
            pb0s[o * TP + pt] = fmaf(a[j], ss0[o], sb0[o]);
        }
    }
    __syncthreads();

    const int w_   = tid >> 5;
    const int lane = tid & 31;

    gemm_stage<0>(XA, XB, g_wT,        32, w_ * 8, ss0, sb0, pb0s, lane);
    __syncthreads();
    gemm_stage<1>(XB, XA, g_wT + 1024, 32, w_ * 8, ss1, sb1, pb0s, lane);
    __syncthreads();
    gemm_stage<2>(XA, red, g_wT + 2048, 64, w_ * 8,      ss2, sb2, pb0s, lane);
    gemm_stage<2>(XA, red, g_wT + 2048, 64, 32 + w_ * 8, ss2, sb2, pb0s, lane);
    __syncthreads();

    // ---- shortcut + mean + final relu; SW read from global (8KB) ----
    {
        int pt  = tid & 15;
        int o0s = (tid >> 4) * 8;      // 8 groups x 8 o = 64 o
        float a[8];
        #pragma unroll
        for (int j = 0; j < 8; j++) a[j] = 0.f;
        #pragma unroll
        for (int j = 0; j < 8; j++) {
            const float* wr = SW + (o0s + j) * 32;
            float acc = 0.f;
            #pragma unroll
            for (int c4 = 0; c4 < 8; c4++) {
                float4 w = *(const float4*)(wr + c4 * 4);
                acc = fmaf(w.x, CF[(c4*4+0) * TP + pt], acc);
                acc = fmaf(w.y, CF[(c4*4+1) * TP + pt], acc);
                acc = fmaf(w.z, CF[(c4*4+2) * TP + pt], acc);
                acc = fmaf(w.w, CF[(c4*4+3) * TP + pt], acc);
            }
            a[j] = acc;
        }
        #pragma unroll
        for (int j = 0; j < 8; j++) {
            int o = o0s + j;
            float v = fmaf(a[j], ssc[o], sbc[o]) + red[o * TP + pt] * (1.0f / 16.0f);
            out[((size_t)b * 64 + o) * NP + p0 + pt] = fmaxf(v, 0.f);
        }
    }
}

// ---------------------------------------------------------------------------
extern "C" void kernel_launch(void* const* d_in, const int* in_sizes, int n_in,
                              void* d_out, int out_size)
{
    (void)in_sizes; (void)n_in; (void)out_size;
    const float* features = (const float*)d_in[1];
    const int*   ef       = (const int*)d_in[2];

    static bool attr_set = false;
    if (!attr_set) {
        cudaFuncSetAttribute(main_kernel,
                             cudaFuncAttributeMaxDynamicSharedMemorySize,
                             SMEM_FLOATS * (int)sizeof(float));
        attr_set = true;
    }

    wprep_kernel<<<16, 256>>>((const float*)d_in[3], (const float*)d_in[6],
                              (const float*)d_in[9]);
    prep_kernel<<<BATCH * 256, 256>>>(ef);
    {
        dim3 tg(EDG / 256, BATCH);
        scatter_kernel<<<tg, 256>>>(ef);
    }
    {
        dim3 tb(32, 8), tg(NP / 32, BATCH);
        transpose_kernel<<<tg, tb>>>(features);
    }
    main_kernel<<<(BATCH * NP) / TP, 128, SMEM_FLOATS * sizeof(float)>>>(
        (const float*)d_in[3],
        (const float*)d_in[4],  (const float*)d_in[5],
        (const float*)d_in[7],  (const float*)d_in[8],
        (const float*)d_in[10], (const float*)d_in[11],
        (const float*)d_in[12], (const float*)d_in[13], (const float*)d_in[14],
        (float*)d_out);
}